// round 16
// baseline (speedup 1.0000x reference)
#include <cuda_runtime.h>
#include <cuda_fp16.h>
#include <cstdint>
#include <math.h>

#define BATCH 8
#define N1 2048
#define N2 2048
#define DIM 512

// Scratch
__device__ float  g_q[(size_t)BATCH * N1 * DIM];                 // 32MB fp32 q
__device__ float  g_attn[(size_t)BATCH * N1 * N2];               // 128MB logits
__device__ __half g_attn_h[(size_t)BATCH * N1 * N2];             // 64MB
__device__ __half g_attn_hT[(size_t)BATCH * N1 * N2];            // 64MB
__device__ __half g_in1T[(size_t)BATCH * DIM * N1];              // 16MB
__device__ __half g_in2T[(size_t)BATCH * DIM * N2];              // 16MB
__device__ __half g_qh[(size_t)BATCH * N1 * DIM];                // 16MB
__device__ __half g_ql[(size_t)BATCH * N1 * DIM];                // 16MB
__device__ __half g_in2h[(size_t)BATCH * N2 * DIM];              // 16MB
__device__ __half g_in2l[(size_t)BATCH * N2 * DIM];              // 16MB

// ---------------- helpers ----------------
__device__ __forceinline__ uint32_t smem_u32(const void* p) {
    uint32_t a;
    asm("{ .reg .u64 t; cvta.to.shared.u64 t, %1; cvt.u32.u64 %0, t; }" : "=r"(a) : "l"(p));
    return a;
}
__device__ __forceinline__ void mma_f16(float* c, const uint32_t* a, const uint32_t* b) {
    asm volatile(
        "mma.sync.aligned.m16n8k16.row.col.f32.f16.f16.f32 "
        "{%0,%1,%2,%3}, {%4,%5,%6,%7}, {%8,%9}, {%0,%1,%2,%3};"
        : "+f"(c[0]), "+f"(c[1]), "+f"(c[2]), "+f"(c[3])
        : "r"(a[0]), "r"(a[1]), "r"(a[2]), "r"(a[3]), "r"(b[0]), "r"(b[1]));
}
__device__ __forceinline__ void ldsm4(uint32_t& r0, uint32_t& r1, uint32_t& r2, uint32_t& r3,
                                      uint32_t addr) {
    asm volatile("ldmatrix.sync.aligned.m8n8.x4.shared.b16 {%0,%1,%2,%3}, [%4];"
                 : "=r"(r0), "=r"(r1), "=r"(r2), "=r"(r3) : "r"(addr));
}
__device__ __forceinline__ void split_h2(float2 v, uint32_t& hi, uint32_t& lo) {
    __half2 h = __float22half2_rn(v);
    hi = *(uint32_t*)&h;
    float2 hf = __half22float2(h);
    __half2 l = __floats2half2_rn(v.x - hf.x, v.y - hf.y);
    lo = *(uint32_t*)&l;
}
__device__ __forceinline__ void cp16(uint32_t dst, const void* src) {
    asm volatile("cp.async.cg.shared.global [%0], [%1], 16;" :: "r"(dst), "l"(src));
}
__device__ __forceinline__ void cp_commit() {
    asm volatile("cp.async.commit_group;" ::: "memory");
}
// all-FMA exp (no MUFU)
__device__ __forceinline__ float fexp(float x) {
    x = fmaxf(x, -87.0f);
    float n = rintf(x * 1.44269504088896f);
    float f = fmaf(n, -0.693147180559945f, x);
    float p = 1.3888889e-3f;
    p = fmaf(p, f, 8.3333333e-3f);
    p = fmaf(p, f, 4.1666667e-2f);
    p = fmaf(p, f, 1.6666667e-1f);
    p = fmaf(p, f, 0.5f);
    p = fmaf(p, f, 1.0f);
    p = fmaf(p, f, 1.0f);
    return p * __int_as_float(((int)n + 127) << 23);
}

// ================= K1: fp16 3-split GEMM from fp32 =================
#define HS 40
#define HTILE_B (128 * HS * 4)
#define HSTAGE  (2 * HTILE_B)
#define HNS 2
template<bool BIAS>
__global__ __launch_bounds__(256, 2)
void hgemm_split(const float* __restrict__ Aall, const float* __restrict__ Ball,
                 const float* __restrict__ bias, float* __restrict__ Call,
                 int K, int lda, int ldb, int ldc,
                 long strideA, long strideB, long strideC)
{
    extern __shared__ char smem_raw[];
    const uint32_t sbase = smem_u32(smem_raw);

    const int tid = threadIdx.x;
    const int lane = tid & 31;
    const int wid = tid >> 5;
    const int wm = wid & 1;
    const int wn = wid >> 1;
    const int g = lane >> 2;
    const int t = lane & 3;
    const int m0 = blockIdx.y * 128;
    const int n0 = blockIdx.x * 128;
    const float* A = Aall + (long)blockIdx.z * strideA;
    const float* B = Ball + (long)blockIdx.z * strideB;
    float* C = Call + (long)blockIdx.z * strideC;

    float acc[4][4][4];
    #pragma unroll
    for (int i = 0; i < 4; i++)
        #pragma unroll
        for (int j = 0; j < 4; j++)
            #pragma unroll
            for (int e = 0; e < 4; e++) acc[i][j][e] = 0.f;

    const int iters = K >> 5;

    auto issue = [&](int it) {
        const int k0 = it << 5;
        const uint32_t st = sbase + (it & (HNS - 1)) * HSTAGE;
        #pragma unroll
        for (int i = 0; i < 4; i++) {
            int ch = tid + 256 * i;
            int r = ch >> 3, c = ch & 7;
            cp16(st + r * (HS * 4) + c * 16, &A[(long)(m0 + r) * lda + k0 + c * 4]);
        }
        #pragma unroll
        for (int i = 0; i < 4; i++) {
            int ch = tid + 256 * i;
            int r = ch >> 3, c = ch & 7;
            cp16(st + HTILE_B + r * (HS * 4) + c * 16, &B[(long)(n0 + r) * ldb + k0 + c * 4]);
        }
    };

    auto compute = [&](int stage) {
        const float* As = (const float*)(smem_raw + (size_t)stage * HSTAGE);
        const float* Bs = (const float*)(smem_raw + (size_t)stage * HSTAGE + HTILE_B);
        const int ar = wm * 64;
        const int br = wn * 32;
        #pragma unroll
        for (int ks = 0; ks < 2; ks++) {
            const int k0f = ks * 16 + 2 * t;
            uint32_t ah[4][4], al[4][4], bh[4][2], bl[4][2];
            #pragma unroll
            for (int mt = 0; mt < 4; mt++) {
                const float* p0 = &As[(ar + mt * 16 + g) * HS];
                const float* p1 = &As[(ar + mt * 16 + g + 8) * HS];
                split_h2(*(const float2*)&p0[k0f],     ah[mt][0], al[mt][0]);
                split_h2(*(const float2*)&p1[k0f],     ah[mt][1], al[mt][1]);
                split_h2(*(const float2*)&p0[k0f + 8], ah[mt][2], al[mt][2]);
                split_h2(*(const float2*)&p1[k0f + 8], ah[mt][3], al[mt][3]);
            }
            #pragma unroll
            for (int nt = 0; nt < 4; nt++) {
                const float* p = &Bs[(br + nt * 8 + g) * HS];
                split_h2(*(const float2*)&p[k0f],     bh[nt][0], bl[nt][0]);
                split_h2(*(const float2*)&p[k0f + 8], bh[nt][1], bl[nt][1]);
            }
            #pragma unroll
            for (int mt = 0; mt < 4; mt++)
                #pragma unroll
                for (int nt = 0; nt < 4; nt++)
                    mma_f16(acc[mt][nt], ah[mt], bh[nt]);
            #pragma unroll
            for (int mt = 0; mt < 4; mt++)
                #pragma unroll
                for (int nt = 0; nt < 4; nt++)
                    mma_f16(acc[mt][nt], al[mt], bh[nt]);
            #pragma unroll
            for (int mt = 0; mt < 4; mt++)
                #pragma unroll
                for (int nt = 0; nt < 4; nt++)
                    mma_f16(acc[mt][nt], ah[mt], bl[nt]);
        }
    };

    #pragma unroll
    for (int s = 0; s < HNS - 1; s++) { issue(s); cp_commit(); }

    for (int it = 0; it < iters; ++it) {
        asm volatile("cp.async.wait_group %0;" :: "n"(HNS - 2) : "memory");
        __syncthreads();
        if (it + HNS - 1 < iters) issue(it + HNS - 1);
        cp_commit();
        compute(it & (HNS - 1));
    }

    #pragma unroll
    for (int mt = 0; mt < 4; mt++) {
        const int r0 = m0 + wm * 64 + mt * 16 + g;
        #pragma unroll
        for (int nt = 0; nt < 4; nt++) {
            const int col = n0 + wn * 32 + nt * 8 + 2 * t;
            float b0 = 0.f, b1 = 0.f;
            if (BIAS) { b0 = bias[col]; b1 = bias[col + 1]; }
            *(float2*)&C[(long)r0 * ldc + col] =
                make_float2(acc[mt][nt][0] + b0, acc[mt][nt][1] + b1);
            *(float2*)&C[(long)(r0 + 8) * ldc + col] =
                make_float2(acc[mt][nt][2] + b0, acc[mt][nt][3] + b1);
        }
    }
}

// ================= K2: 3-term GEMM, pre-split fp16, ldmatrix =================
#define PS 40
#define PTILE_B (128 * PS * 2)          // 10240
#define PSTAGE  (4 * PTILE_B)           // 40960
#define PNS 2
__global__ __launch_bounds__(256, 2)
void hgemm3(const __half* __restrict__ Ahall, const __half* __restrict__ Alall,
            const __half* __restrict__ Bhall, const __half* __restrict__ Blall,
            float* __restrict__ Cfall,
            int K, int lda, int ldb, int ldc,
            long strideA, long strideB, long strideC)
{
    extern __shared__ char smem_raw[];
    const uint32_t sbase = smem_u32(smem_raw);

    const int tid = threadIdx.x;
    const int lane = tid & 31;
    const int wid = tid >> 5;
    const int wm = wid & 1;
    const int wn = wid >> 1;
    const int m0 = blockIdx.y * 128;
    const int n0 = blockIdx.x * 128;
    const __half* Ah = Ahall + (long)blockIdx.z * strideA;
    const __half* Al = Alall + (long)blockIdx.z * strideA;
    const __half* Bh = Bhall + (long)blockIdx.z * strideB;
    const __half* Bl = Blall + (long)blockIdx.z * strideB;
    float* C = Cfall + (long)blockIdx.z * strideC;

    const int a_r = (lane & 7) + ((lane >> 3) & 1) * 8;
    const int a_c = (lane >> 4) * 8;
    const int b_r = (lane & 7) + (lane >> 4) * 8;
    const int b_c = ((lane >> 3) & 1) * 8;

    float acc[4][4][4];
    #pragma unroll
    for (int i = 0; i < 4; i++)
        #pragma unroll
        for (int j = 0; j < 4; j++)
            #pragma unroll
            for (int e = 0; e < 4; e++) acc[i][j][e] = 0.f;

    const int iters = K >> 5;

    auto issue = [&](int it) {
        const int k0 = it << 5;
        const uint32_t st = sbase + (it & (PNS - 1)) * PSTAGE;
        #pragma unroll
        for (int i = 0; i < 2; i++) {
            int ch = tid + 256 * i;
            int r = ch >> 2, c = ch & 3;
            uint32_t off = r * (PS * 2) + c * 16;
            long goff = (long)(m0 + r) * lda + k0 + c * 8;
            cp16(st + off, &Ah[goff]);
            cp16(st + PTILE_B + off, &Al[goff]);
        }
        #pragma unroll
        for (int i = 0; i < 2; i++) {
            int ch = tid + 256 * i;
            int r = ch >> 2, c = ch & 3;
            uint32_t off = r * (PS * 2) + c * 16;
            long goff = (long)(n0 + r) * ldb + k0 + c * 8;
            cp16(st + 2 * PTILE_B + off, &Bh[goff]);
            cp16(st + 3 * PTILE_B + off, &Bl[goff]);
        }
    };

    auto compute = [&](int stage) {
        const uint32_t base = sbase + (uint32_t)stage * PSTAGE;
        const uint32_t aA = base + (((wm * 64 + a_r) * PS) + a_c) * 2;
        const uint32_t aB = base + 2 * PTILE_B + (((wn * 32 + b_r) * PS) + b_c) * 2;
        #pragma unroll
        for (int ks = 0; ks < 2; ks++) {
            const uint32_t kofs = ks * 32;
            uint32_t bh[4][2], bl[4][2];
            #pragma unroll
            for (int p = 0; p < 2; p++) {
                const uint32_t addr = aB + p * (16 * PS * 2) + kofs;
                ldsm4(bh[2 * p][0], bh[2 * p][1], bh[2 * p + 1][0], bh[2 * p + 1][1], addr);
                ldsm4(bl[2 * p][0], bl[2 * p][1], bl[2 * p + 1][0], bl[2 * p + 1][1],
                      addr + PTILE_B);
            }
            #pragma unroll
            for (int mt = 0; mt < 4; mt++) {
                const uint32_t addr = aA + mt * (16 * PS * 2) + kofs;
                uint32_t ah[4], al[4];
                ldsm4(ah[0], ah[1], ah[2], ah[3], addr);
                ldsm4(al[0], al[1], al[2], al[3], addr + PTILE_B);
                #pragma unroll
                for (int nt = 0; nt < 4; nt++)
                    mma_f16(acc[mt][nt], ah, bh[nt]);
                #pragma unroll
                for (int nt = 0; nt < 4; nt++)
                    mma_f16(acc[mt][nt], al, bh[nt]);
                #pragma unroll
                for (int nt = 0; nt < 4; nt++)
                    mma_f16(acc[mt][nt], ah, bl[nt]);
            }
        }
    };

    #pragma unroll
    for (int s = 0; s < PNS - 1; s++) { issue(s); cp_commit(); }

    for (int it = 0; it < iters; ++it) {
        asm volatile("cp.async.wait_group %0;" :: "n"(PNS - 2) : "memory");
        __syncthreads();
        if (it + PNS - 1 < iters) issue(it + PNS - 1);
        cp_commit();
        compute(it & (PNS - 1));
    }

    const int g = lane >> 2;
    const int t = lane & 3;
    #pragma unroll
    for (int mt = 0; mt < 4; mt++) {
        const int r0 = m0 + wm * 64 + mt * 16 + g;
        #pragma unroll
        for (int nt = 0; nt < 4; nt++) {
            const int col = n0 + wn * 32 + nt * 8 + 2 * t;
            *(float2*)&C[(long)r0 * ldc + col] = make_float2(acc[mt][nt][0], acc[mt][nt][1]);
            *(float2*)&C[(long)(r0 + 8) * ldc + col] = make_float2(acc[mt][nt][2], acc[mt][nt][3]);
        }
    }
}

// ================= K4+K5 fused: fp16 single-pass GEMM, ldmatrix =================
#define GS 40
#define GTILE_B (128 * GS * 2)
#define GSTAGE  (2 * GTILE_B)
#define GNS 4
__global__ __launch_bounds__(256, 2)
void tgemm_h2(const __half* __restrict__ A0, const __half* __restrict__ B0,
              float* __restrict__ C0,
              const __half* __restrict__ A1, const __half* __restrict__ B1,
              float* __restrict__ C1,
              int K, int lda, int ldb, int ldc,
              long strideA, long strideB, long strideC)
{
    extern __shared__ char smem_raw[];
    const uint32_t sbase = smem_u32(smem_raw);

    const int tid = threadIdx.x;
    const int lane = tid & 31;
    const int wid = tid >> 5;
    const int wm = wid & 1;
    const int wn = wid >> 1;
    const int m0 = blockIdx.y * 128;
    const int n0 = blockIdx.x * 128;
    const int z = blockIdx.z;
    const int zz = z & (BATCH - 1);
    const bool second = z >= BATCH;
    const __half* A = (second ? A1 : A0) + (long)zz * strideA;
    const __half* B = (second ? B1 : B0) + (long)zz * strideB;
    float* C = (second ? C1 : C0) + (long)zz * strideC;

    const int a_r = (lane & 7) + ((lane >> 3) & 1) * 8;
    const int a_c = (lane >> 4) * 8;
    const int b_r = (lane & 7) + (lane >> 4) * 8;
    const int b_c = ((lane >> 3) & 1) * 8;

    float acc[4][4][4];
    #pragma unroll
    for (int i = 0; i < 4; i++)
        #pragma unroll
        for (int j = 0; j < 4; j++)
            #pragma unroll
            for (int e = 0; e < 4; e++) acc[i][j][e] = 0.f;

    const int iters = K >> 5;

    auto issue = [&](int it) {
        const int k0 = it << 5;
        const uint32_t st = sbase + (it & (GNS - 1)) * GSTAGE;
        #pragma unroll
        for (int i = 0; i < 2; i++) {
            int ch = tid + 256 * i;
            int r = ch >> 2, c = ch & 3;
            cp16(st + r * (GS * 2) + c * 16, &A[(long)(m0 + r) * lda + k0 + c * 8]);
        }
        #pragma unroll
        for (int i = 0; i < 2; i++) {
            int ch = tid + 256 * i;
            int r = ch >> 2, c = ch & 3;
            cp16(st + GTILE_B + r * (GS * 2) + c * 16, &B[(long)(n0 + r) * ldb + k0 + c * 8]);
        }
    };

    auto compute = [&](int stage) {
        const uint32_t base = sbase + (uint32_t)stage * GSTAGE;
        const uint32_t aA = base + (((wm * 64 + a_r) * GS) + a_c) * 2;
        const uint32_t aB = base + GTILE_B + (((wn * 32 + b_r) * GS) + b_c) * 2;
        #pragma unroll
        for (int ks = 0; ks < 2; ks++) {
            const uint32_t kofs = ks * 32;
            uint32_t b[4][2];
            #pragma unroll
            for (int p = 0; p < 2; p++) {
                ldsm4(b[2 * p][0], b[2 * p][1], b[2 * p + 1][0], b[2 * p + 1][1],
                      aB + p * (16 * GS * 2) + kofs);
            }
            #pragma unroll
            for (int mt = 0; mt < 4; mt++) {
                uint32_t a[4];
                ldsm4(a[0], a[1], a[2], a[3], aA + mt * (16 * GS * 2) + kofs);
                #pragma unroll
                for (int nt = 0; nt < 4; nt++)
                    mma_f16(acc[mt][nt], a, b[nt]);
            }
        }
    };

    #pragma unroll
    for (int s = 0; s < GNS - 1; s++) { issue(s); cp_commit(); }

    for (int it = 0; it < iters; ++it) {
        asm volatile("cp.async.wait_group %0;" :: "n"(GNS - 2) : "memory");
        __syncthreads();
        if (it + GNS - 1 < iters) issue(it + GNS - 1);
        cp_commit();
        compute(it & (GNS - 1));
    }

    const int g = lane >> 2;
    const int t = lane & 3;
    #pragma unroll
    for (int mt = 0; mt < 4; mt++) {
        const int r0 = m0 + wm * 64 + mt * 16 + g;
        #pragma unroll
        for (int nt = 0; nt < 4; nt++) {
            const int col = n0 + wn * 32 + nt * 8 + 2 * t;
            *(float2*)&C[(long)r0 * ldc + col] = make_float2(acc[mt][nt][0], acc[mt][nt][1]);
            *(float2*)&C[(long)(r0 + 8) * ldc + col] = make_float2(acc[mt][nt][2], acc[mt][nt][3]);
        }
    }
}

// ---------------- softmax rows of 2048: fp32 logits -> fp16 attn ----------------
__global__ __launch_bounds__(256)
void softmax2048_kernel(const float* __restrict__ logits, __half* __restrict__ attn_h)
{
    const long row = blockIdx.x;
    const float* p = logits + row * (long)N2;
    const int tid = threadIdx.x;

    float4 v0 = *(const float4*)(p + tid * 8);
    float4 v1 = *(const float4*)(p + tid * 8 + 4);

    float mx = fmaxf(fmaxf(fmaxf(v0.x, v0.y), fmaxf(v0.z, v0.w)),
                     fmaxf(fmaxf(v1.x, v1.y), fmaxf(v1.z, v1.w)));
    __shared__ float red[8];
    #pragma unroll
    for (int o = 16; o > 0; o >>= 1) mx = fmaxf(mx, __shfl_xor_sync(0xffffffffu, mx, o));
    if ((tid & 31) == 0) red[tid >> 5] = mx;
    __syncthreads();
    mx = red[0];
    #pragma unroll
    for (int i = 1; i < 8; i++) mx = fmaxf(mx, red[i]);
    __syncthreads();

    float e0 = fexp(v0.x - mx), e1 = fexp(v0.y - mx), e2 = fexp(v0.z - mx), e3 = fexp(v0.w - mx);
    float e4 = fexp(v1.x - mx), e5 = fexp(v1.y - mx), e6 = fexp(v1.z - mx), e7 = fexp(v1.w - mx);
    float s = ((e0 + e1) + (e2 + e3)) + ((e4 + e5) + (e6 + e7));
    #pragma unroll
    for (int o = 16; o > 0; o >>= 1) s += __shfl_xor_sync(0xffffffffu, s, o);
    if ((tid & 31) == 0) red[tid >> 5] = s;
    __syncthreads();
    s = 0.f;
    #pragma unroll
    for (int i = 0; i < 8; i++) s += red[i];
    const float inv = 1.0f / s;

    __half2 h[4];
    h[0] = __floats2half2_rn(e0 * inv, e1 * inv);
    h[1] = __floats2half2_rn(e2 * inv, e3 * inv);
    h[2] = __floats2half2_rn(e4 * inv, e5 * inv);
    h[3] = __floats2half2_rn(e6 * inv, e7 * inv);
    *(uint4*)(attn_h + row * (long)N2 + tid * 8) = *(uint4*)h;
}

// ---------------- fp16 transpose ----------------
__global__ __launch_bounds__(256)
void transpose_h(const __half* __restrict__ in, __half* __restrict__ out, int R, int Cc)
{
    __shared__ __half S[64][65];
    const long zin = (long)blockIdx.z * R * Cc;
    const int x0 = blockIdx.x * 64;
    const int y0 = blockIdx.y * 64;
    const int tid = threadIdx.x;

    #pragma unroll
    for (int i = 0; i < 8; i++) {
        int idx = tid + 256 * i;
        int r = idx >> 5, c2 = idx & 31;
        __half2 v = *(const __half2*)&in[zin + (long)(y0 + r) * Cc + x0 + 2 * c2];
        S[r][2 * c2] = __low2half(v);
        S[r][2 * c2 + 1] = __high2half(v);
    }
    __syncthreads();
    #pragma unroll
    for (int i = 0; i < 8; i++) {
        int idx = tid + 256 * i;
        int cc = idx >> 5, r2 = idx & 31;
        __half2 v = __halves2half2(S[2 * r2][cc], S[2 * r2 + 1][cc]);
        *(__half2*)&out[zin + (long)(x0 + cc) * R + y0 + 2 * r2] = v;
    }
}

// ---------------- fp32 -> fp16 transpose ----------------
__global__ __launch_bounds__(256)
void transpose_f2h(const float* __restrict__ in, __half* __restrict__ out, int R, int Cc)
{
    __shared__ __half S[64][65];
    const long zo = (long)blockIdx.z * R * Cc;
    const int x0 = blockIdx.x * 64;
    const int y0 = blockIdx.y * 64;
    const int tid = threadIdx.x;

    #pragma unroll
    for (int i = 0; i < 8; i++) {
        int idx = tid + 256 * i;
        int r = idx >> 5, c2 = idx & 31;
        float2 v = *(const float2*)&in[zo + (long)(y0 + r) * Cc + x0 + 2 * c2];
        S[r][2 * c2] = __float2half_rn(v.x);
        S[r][2 * c2 + 1] = __float2half_rn(v.y);
    }
    __syncthreads();
    #pragma unroll
    for (int i = 0; i < 8; i++) {
        int idx = tid + 256 * i;
        int cc = idx >> 5, r2 = idx & 31;
        __half2 v = __halves2half2(S[2 * r2][cc], S[2 * r2 + 1][cc]);
        *(__half2*)&out[zo + (long)(x0 + cc) * R + y0 + 2 * r2] = v;
    }
}

// ---------------- fused prep: fp32 [R][C] -> T [C][R] fp16 + hi/lo [R][C] fp16 ----------------
__global__ __launch_bounds__(256)
void prep_in(const float* __restrict__ in, __half* __restrict__ T,
             __half* __restrict__ outh, __half* __restrict__ outl, int R, int Cc)
{
    __shared__ __half S[64][65];
    const long zo = (long)blockIdx.z * R * Cc;
    const int x0 = blockIdx.x * 64;
    const int y0 = blockIdx.y * 64;
    const int tid = threadIdx.x;

    #pragma unroll
    for (int i = 0; i < 8; i++) {
        int idx = tid + 256 * i;
        int r = idx >> 5, c2 = idx & 31;
        long gi = zo + (long)(y0 + r) * Cc + x0 + 2 * c2;
        float2 v = *(const float2*)&in[gi];
        uint32_t hh, ll;
        split_h2(v, hh, ll);
        *(uint32_t*)&outh[gi] = hh;
        *(uint32_t*)&outl[gi] = ll;
        __half2 h2v = *(__half2*)&hh;
        S[r][2 * c2] = __low2half(h2v);
        S[r][2 * c2 + 1] = __high2half(h2v);
    }
    __syncthreads();
    #pragma unroll
    for (int i = 0; i < 8; i++) {
        int idx = tid + 256 * i;
        int cc = idx >> 5, r2 = idx & 31;
        __half2 v = __halves2half2(S[2 * r2][cc], S[2 * r2 + 1][cc]);
        *(__half2*)&T[zo + (long)(x0 + cc) * R + y0 + 2 * r2] = v;
    }
}

// ---------------- fp32 -> (hi, lo) fp16 convert ----------------
__global__ __launch_bounds__(256)
void convert_hl(const float* __restrict__ in, __half* __restrict__ outh,
                __half* __restrict__ outl, long n)
{
    long i = ((long)blockIdx.x * 256 + threadIdx.x) * 8;
    if (i >= n) return;
    float4 v0 = *(const float4*)&in[i];
    float4 v1 = *(const float4*)&in[i + 4];
    uint32_t h[4], l[4];
    split_h2(make_float2(v0.x, v0.y), h[0], l[0]);
    split_h2(make_float2(v0.z, v0.w), h[1], l[1]);
    split_h2(make_float2(v1.x, v1.y), h[2], l[2]);
    split_h2(make_float2(v1.z, v1.w), h[3], l[3]);
    *(uint4*)&outh[i] = make_uint4(h[0], h[1], h[2], h[3]);
    *(uint4*)&outl[i] = make_uint4(l[0], l[1], l[2], l[3]);
}

// ---------------- launcher ----------------
extern "C" void kernel_launch(void* const* d_in, const int* in_sizes, int n_in,
                              void* d_out, int out_size)
{
    const float* input1 = (const float*)d_in[0];
    const float* input2 = (const float*)d_in[1];
    const float* W_w    = (const float*)d_in[2];
    const float* W_b    = (const float*)d_in[3];

    float* out1 = (float*)d_out;
    float* out2 = out1 + (long)BATCH * N1 * DIM;

    float *q, *attn;
    __half *attn_h, *attn_hT, *in1T, *in2T, *qh, *ql, *in2h, *in2l;
    cudaGetSymbolAddress((void**)&q, g_q);
    cudaGetSymbolAddress((void**)&attn, g_attn);
    cudaGetSymbolAddress((void**)&attn_h, g_attn_h);
    cudaGetSymbolAddress((void**)&attn_hT, g_attn_hT);
    cudaGetSymbolAddress((void**)&in1T, g_in1T);
    cudaGetSymbolAddress((void**)&in2T, g_in2T);
    cudaGetSymbolAddress((void**)&qh, g_qh);
    cudaGetSymbolAddress((void**)&ql, g_ql);
    cudaGetSymbolAddress((void**)&in2h, g_in2h);
    cudaGetSymbolAddress((void**)&in2l, g_in2l);

    const int SM_H = HNS * HSTAGE;   // 81920
    const int SM_P = PNS * PSTAGE;   // 81920
    const int SM_G = GNS * GSTAGE;   // 81920

    cudaFuncSetAttribute(hgemm_split<true>, cudaFuncAttributeMaxDynamicSharedMemorySize, SM_H);
    cudaFuncSetAttribute(hgemm3, cudaFuncAttributeMaxDynamicSharedMemorySize, SM_P);
    cudaFuncSetAttribute(tgemm_h2, cudaFuncAttributeMaxDynamicSharedMemorySize, SM_G);

    // Prep: input1 -> in1T ; input2 -> in2T + in2h/in2l in ONE pass
    transpose_f2h<<<dim3(DIM / 64, N1 / 64, BATCH), 256>>>(input1, in1T, N1, DIM);
    prep_in<<<dim3(DIM / 64, N2 / 64, BATCH), 256>>>(input2, in2T, in2h, in2l, N2, DIM);

    // K1: q = input1 @ W^T + b (fp32 out)
    hgemm_split<true><<<dim3(DIM / 128, (BATCH * N1) / 128, 1), 256, SM_H>>>(
        input1, W_w, W_b, q, DIM, DIM, DIM, DIM, 0L, 0L, 0L);

    // convert q -> qh/ql fp16
    {
        long n = (long)BATCH * N1 * DIM;
        convert_hl<<<(int)(n / (256 * 8)), 256>>>(q, qh, ql, n);
    }

    // K2: logits = q @ input2^T per batch (3-term pre-split, ldmatrix)
    hgemm3<<<dim3(N2 / 128, N1 / 128, BATCH), 256, SM_P>>>(
        qh, ql, in2h, in2l, attn, DIM, DIM, DIM, N2,
        (long)N1 * DIM, (long)N2 * DIM, (long)N1 * N2);

    // softmax: fp32 logits -> fp16 attn
    softmax2048_kernel<<<BATCH * N1, 256>>>(attn, attn_h);

    // attn^T (materialized)
    transpose_h<<<dim3(N2 / 64, N1 / 64, BATCH), 256>>>(attn_h, attn_hT, N1, N2);

    // K4 + K5 fused
    tgemm_h2<<<dim3(DIM / 128, N1 / 128, 2 * BATCH), 256, SM_G>>>(
        attn_h, in2T, out1,
        attn_hT, in1T, out2,
        N2, N2, N2, DIM,
        (long)N1 * N2, (long)DIM * N2, (long)N1 * DIM);
}

// round 17
// speedup vs baseline: 1.5150x; 1.5150x over previous
#include <cuda_runtime.h>
#include <cuda_fp16.h>
#include <cstdint>
#include <math.h>

#define BATCH 8
#define N1 2048
#define N2 2048
#define DIM 512

// Scratch
__device__ float  g_attn[(size_t)BATCH * N1 * N2];               // 128MB logits
__device__ __half g_attn_h[(size_t)BATCH * N1 * N2];             // 64MB
__device__ __half g_attn_hT[(size_t)BATCH * N1 * N2];            // 64MB
__device__ __half g_in1T[(size_t)BATCH * DIM * N1];              // 16MB
__device__ __half g_in2T[(size_t)BATCH * DIM * N2];              // 16MB
__device__ __half g_qh[(size_t)BATCH * N1 * DIM];                // 16MB
__device__ __half g_ql[(size_t)BATCH * N1 * DIM];                // 16MB
__device__ __half g_in2h[(size_t)BATCH * N2 * DIM];              // 16MB
__device__ __half g_in2l[(size_t)BATCH * N2 * DIM];              // 16MB

// ---------------- helpers ----------------
__device__ __forceinline__ uint32_t smem_u32(const void* p) {
    uint32_t a;
    asm("{ .reg .u64 t; cvta.to.shared.u64 t, %1; cvt.u32.u64 %0, t; }" : "=r"(a) : "l"(p));
    return a;
}
__device__ __forceinline__ void mma_f16(float* c, const uint32_t* a, const uint32_t* b) {
    asm volatile(
        "mma.sync.aligned.m16n8k16.row.col.f32.f16.f16.f32 "
        "{%0,%1,%2,%3}, {%4,%5,%6,%7}, {%8,%9}, {%0,%1,%2,%3};"
        : "+f"(c[0]), "+f"(c[1]), "+f"(c[2]), "+f"(c[3])
        : "r"(a[0]), "r"(a[1]), "r"(a[2]), "r"(a[3]), "r"(b[0]), "r"(b[1]));
}
__device__ __forceinline__ void ldsm4(uint32_t& r0, uint32_t& r1, uint32_t& r2, uint32_t& r3,
                                      uint32_t addr) {
    asm volatile("ldmatrix.sync.aligned.m8n8.x4.shared.b16 {%0,%1,%2,%3}, [%4];"
                 : "=r"(r0), "=r"(r1), "=r"(r2), "=r"(r3) : "r"(addr));
}
__device__ __forceinline__ void split_h2(float2 v, uint32_t& hi, uint32_t& lo) {
    __half2 h = __float22half2_rn(v);
    hi = *(uint32_t*)&h;
    float2 hf = __half22float2(h);
    __half2 l = __floats2half2_rn(v.x - hf.x, v.y - hf.y);
    lo = *(uint32_t*)&l;
}
__device__ __forceinline__ void cp16(uint32_t dst, const void* src) {
    asm volatile("cp.async.cg.shared.global [%0], [%1], 16;" :: "r"(dst), "l"(src));
}
__device__ __forceinline__ void cp_commit() {
    asm volatile("cp.async.commit_group;" ::: "memory");
}
// all-FMA exp (no MUFU)
__device__ __forceinline__ float fexp(float x) {
    x = fmaxf(x, -87.0f);
    float n = rintf(x * 1.44269504088896f);
    float f = fmaf(n, -0.693147180559945f, x);
    float p = 1.3888889e-3f;
    p = fmaf(p, f, 8.3333333e-3f);
    p = fmaf(p, f, 4.1666667e-2f);
    p = fmaf(p, f, 1.6666667e-1f);
    p = fmaf(p, f, 0.5f);
    p = fmaf(p, f, 1.0f);
    p = fmaf(p, f, 1.0f);
    return p * __int_as_float(((int)n + 127) << 23);
}

// ================= K1: fp16 3-split GEMM from fp32, epilogue writes qh/ql =================
#define HS 40
#define HTILE_B (128 * HS * 4)
#define HSTAGE  (2 * HTILE_B)
#define HNS 2
__global__ __launch_bounds__(256, 2)
void hgemm_split_q(const float* __restrict__ A, const float* __restrict__ B,
                   const float* __restrict__ bias,
                   __half* __restrict__ Ch, __half* __restrict__ Cl,
                   int K, int lda, int ldb, int ldc)
{
    extern __shared__ char smem_raw[];
    const uint32_t sbase = smem_u32(smem_raw);

    const int tid = threadIdx.x;
    const int lane = tid & 31;
    const int wid = tid >> 5;
    const int wm = wid & 1;
    const int wn = wid >> 1;
    const int g = lane >> 2;
    const int t = lane & 3;
    const int m0 = blockIdx.y * 128;
    const int n0 = blockIdx.x * 128;

    float acc[4][4][4];
    #pragma unroll
    for (int i = 0; i < 4; i++)
        #pragma unroll
        for (int j = 0; j < 4; j++)
            #pragma unroll
            for (int e = 0; e < 4; e++) acc[i][j][e] = 0.f;

    const int iters = K >> 5;

    auto issue = [&](int it) {
        const int k0 = it << 5;
        const uint32_t st = sbase + (it & (HNS - 1)) * HSTAGE;
        #pragma unroll
        for (int i = 0; i < 4; i++) {
            int ch = tid + 256 * i;
            int r = ch >> 3, c = ch & 7;
            cp16(st + r * (HS * 4) + c * 16, &A[(long)(m0 + r) * lda + k0 + c * 4]);
        }
        #pragma unroll
        for (int i = 0; i < 4; i++) {
            int ch = tid + 256 * i;
            int r = ch >> 3, c = ch & 7;
            cp16(st + HTILE_B + r * (HS * 4) + c * 16, &B[(long)(n0 + r) * ldb + k0 + c * 4]);
        }
    };

    auto compute = [&](int stage) {
        const float* As = (const float*)(smem_raw + (size_t)stage * HSTAGE);
        const float* Bs = (const float*)(smem_raw + (size_t)stage * HSTAGE + HTILE_B);
        const int ar = wm * 64;
        const int br = wn * 32;
        #pragma unroll
        for (int ks = 0; ks < 2; ks++) {
            const int k0f = ks * 16 + 2 * t;
            uint32_t ah[4][4], al[4][4], bh[4][2], bl[4][2];
            #pragma unroll
            for (int mt = 0; mt < 4; mt++) {
                const float* p0 = &As[(ar + mt * 16 + g) * HS];
                const float* p1 = &As[(ar + mt * 16 + g + 8) * HS];
                split_h2(*(const float2*)&p0[k0f],     ah[mt][0], al[mt][0]);
                split_h2(*(const float2*)&p1[k0f],     ah[mt][1], al[mt][1]);
                split_h2(*(const float2*)&p0[k0f + 8], ah[mt][2], al[mt][2]);
                split_h2(*(const float2*)&p1[k0f + 8], ah[mt][3], al[mt][3]);
            }
            #pragma unroll
            for (int nt = 0; nt < 4; nt++) {
                const float* p = &Bs[(br + nt * 8 + g) * HS];
                split_h2(*(const float2*)&p[k0f],     bh[nt][0], bl[nt][0]);
                split_h2(*(const float2*)&p[k0f + 8], bh[nt][1], bl[nt][1]);
            }
            #pragma unroll
            for (int mt = 0; mt < 4; mt++)
                #pragma unroll
                for (int nt = 0; nt < 4; nt++)
                    mma_f16(acc[mt][nt], ah[mt], bh[nt]);
            #pragma unroll
            for (int mt = 0; mt < 4; mt++)
                #pragma unroll
                for (int nt = 0; nt < 4; nt++)
                    mma_f16(acc[mt][nt], al[mt], bh[nt]);
            #pragma unroll
            for (int mt = 0; mt < 4; mt++)
                #pragma unroll
                for (int nt = 0; nt < 4; nt++)
                    mma_f16(acc[mt][nt], ah[mt], bl[nt]);
        }
    };

    #pragma unroll
    for (int s = 0; s < HNS - 1; s++) { issue(s); cp_commit(); }

    for (int it = 0; it < iters; ++it) {
        asm volatile("cp.async.wait_group %0;" :: "n"(HNS - 2) : "memory");
        __syncthreads();
        if (it + HNS - 1 < iters) issue(it + HNS - 1);
        cp_commit();
        compute(it & (HNS - 1));
    }

    // epilogue: add bias, split to (hi, lo) fp16, store both
    #pragma unroll
    for (int mt = 0; mt < 4; mt++) {
        const int r0 = m0 + wm * 64 + mt * 16 + g;
        #pragma unroll
        for (int nt = 0; nt < 4; nt++) {
            const int col = n0 + wn * 32 + nt * 8 + 2 * t;
            float b0 = bias[col], b1 = bias[col + 1];
            uint32_t h, l;
            split_h2(make_float2(acc[mt][nt][0] + b0, acc[mt][nt][1] + b1), h, l);
            *(uint32_t*)&Ch[(long)r0 * ldc + col] = h;
            *(uint32_t*)&Cl[(long)r0 * ldc + col] = l;
            split_h2(make_float2(acc[mt][nt][2] + b0, acc[mt][nt][3] + b1), h, l);
            *(uint32_t*)&Ch[(long)(r0 + 8) * ldc + col] = h;
            *(uint32_t*)&Cl[(long)(r0 + 8) * ldc + col] = l;
        }
    }
}

// ================= K2: 3-term GEMM, pre-split fp16, ldmatrix =================
#define PS 40
#define PTILE_B (128 * PS * 2)          // 10240
#define PSTAGE  (4 * PTILE_B)           // 40960
#define PNS 2
__global__ __launch_bounds__(256, 2)
void hgemm3(const __half* __restrict__ Ahall, const __half* __restrict__ Alall,
            const __half* __restrict__ Bhall, const __half* __restrict__ Blall,
            float* __restrict__ Cfall,
            int K, int lda, int ldb, int ldc,
            long strideA, long strideB, long strideC)
{
    extern __shared__ char smem_raw[];
    const uint32_t sbase = smem_u32(smem_raw);

    const int tid = threadIdx.x;
    const int lane = tid & 31;
    const int wid = tid >> 5;
    const int wm = wid & 1;
    const int wn = wid >> 1;
    const int m0 = blockIdx.y * 128;
    const int n0 = blockIdx.x * 128;
    const __half* Ah = Ahall + (long)blockIdx.z * strideA;
    const __half* Al = Alall + (long)blockIdx.z * strideA;
    const __half* Bh = Bhall + (long)blockIdx.z * strideB;
    const __half* Bl = Blall + (long)blockIdx.z * strideB;
    float* C = Cfall + (long)blockIdx.z * strideC;

    const int a_r = (lane & 7) + ((lane >> 3) & 1) * 8;
    const int a_c = (lane >> 4) * 8;
    const int b_r = (lane & 7) + (lane >> 4) * 8;
    const int b_c = ((lane >> 3) & 1) * 8;

    float acc[4][4][4];
    #pragma unroll
    for (int i = 0; i < 4; i++)
        #pragma unroll
        for (int j = 0; j < 4; j++)
            #pragma unroll
            for (int e = 0; e < 4; e++) acc[i][j][e] = 0.f;

    const int iters = K >> 5;

    auto issue = [&](int it) {
        const int k0 = it << 5;
        const uint32_t st = sbase + (it & (PNS - 1)) * PSTAGE;
        #pragma unroll
        for (int i = 0; i < 2; i++) {
            int ch = tid + 256 * i;
            int r = ch >> 2, c = ch & 3;
            uint32_t off = r * (PS * 2) + c * 16;
            long goff = (long)(m0 + r) * lda + k0 + c * 8;
            cp16(st + off, &Ah[goff]);
            cp16(st + PTILE_B + off, &Al[goff]);
        }
        #pragma unroll
        for (int i = 0; i < 2; i++) {
            int ch = tid + 256 * i;
            int r = ch >> 2, c = ch & 3;
            uint32_t off = r * (PS * 2) + c * 16;
            long goff = (long)(n0 + r) * ldb + k0 + c * 8;
            cp16(st + 2 * PTILE_B + off, &Bh[goff]);
            cp16(st + 3 * PTILE_B + off, &Bl[goff]);
        }
    };

    auto compute = [&](int stage) {
        const uint32_t base = sbase + (uint32_t)stage * PSTAGE;
        const uint32_t aA = base + (((wm * 64 + a_r) * PS) + a_c) * 2;
        const uint32_t aB = base + 2 * PTILE_B + (((wn * 32 + b_r) * PS) + b_c) * 2;
        #pragma unroll
        for (int ks = 0; ks < 2; ks++) {
            const uint32_t kofs = ks * 32;
            uint32_t bh[4][2], bl[4][2];
            #pragma unroll
            for (int p = 0; p < 2; p++) {
                const uint32_t addr = aB + p * (16 * PS * 2) + kofs;
                ldsm4(bh[2 * p][0], bh[2 * p][1], bh[2 * p + 1][0], bh[2 * p + 1][1], addr);
                ldsm4(bl[2 * p][0], bl[2 * p][1], bl[2 * p + 1][0], bl[2 * p + 1][1],
                      addr + PTILE_B);
            }
            #pragma unroll
            for (int mt = 0; mt < 4; mt++) {
                const uint32_t addr = aA + mt * (16 * PS * 2) + kofs;
                uint32_t ah[4], al[4];
                ldsm4(ah[0], ah[1], ah[2], ah[3], addr);
                ldsm4(al[0], al[1], al[2], al[3], addr + PTILE_B);
                #pragma unroll
                for (int nt = 0; nt < 4; nt++)
                    mma_f16(acc[mt][nt], ah, bh[nt]);
                #pragma unroll
                for (int nt = 0; nt < 4; nt++)
                    mma_f16(acc[mt][nt], al, bh[nt]);
                #pragma unroll
                for (int nt = 0; nt < 4; nt++)
                    mma_f16(acc[mt][nt], ah, bl[nt]);
            }
        }
    };

    #pragma unroll
    for (int s = 0; s < PNS - 1; s++) { issue(s); cp_commit(); }

    for (int it = 0; it < iters; ++it) {
        asm volatile("cp.async.wait_group %0;" :: "n"(PNS - 2) : "memory");
        __syncthreads();
        if (it + PNS - 1 < iters) issue(it + PNS - 1);
        cp_commit();
        compute(it & (PNS - 1));
    }

    const int g = lane >> 2;
    const int t = lane & 3;
    #pragma unroll
    for (int mt = 0; mt < 4; mt++) {
        const int r0 = m0 + wm * 64 + mt * 16 + g;
        #pragma unroll
        for (int nt = 0; nt < 4; nt++) {
            const int col = n0 + wn * 32 + nt * 8 + 2 * t;
            *(float2*)&C[(long)r0 * ldc + col] = make_float2(acc[mt][nt][0], acc[mt][nt][1]);
            *(float2*)&C[(long)(r0 + 8) * ldc + col] = make_float2(acc[mt][nt][2], acc[mt][nt][3]);
        }
    }
}

// ================= K4+K5 fused: fp16 single-pass GEMM, ldmatrix =================
#define GS 40
#define GTILE_B (128 * GS * 2)
#define GSTAGE  (2 * GTILE_B)
#define GNS 4
__global__ __launch_bounds__(256, 2)
void tgemm_h2(const __half* __restrict__ A0, const __half* __restrict__ B0,
              float* __restrict__ C0,
              const __half* __restrict__ A1, const __half* __restrict__ B1,
              float* __restrict__ C1,
              int K, int lda, int ldb, int ldc,
              long strideA, long strideB, long strideC)
{
    extern __shared__ char smem_raw[];
    const uint32_t sbase = smem_u32(smem_raw);

    const int tid = threadIdx.x;
    const int lane = tid & 31;
    const int wid = tid >> 5;
    const int wm = wid & 1;
    const int wn = wid >> 1;
    const int m0 = blockIdx.y * 128;
    const int n0 = blockIdx.x * 128;
    const int z = blockIdx.z;
    const int zz = z & (BATCH - 1);
    const bool second = z >= BATCH;
    const __half* A = (second ? A1 : A0) + (long)zz * strideA;
    const __half* B = (second ? B1 : B0) + (long)zz * strideB;
    float* C = (second ? C1 : C0) + (long)zz * strideC;

    const int a_r = (lane & 7) + ((lane >> 3) & 1) * 8;
    const int a_c = (lane >> 4) * 8;
    const int b_r = (lane & 7) + (lane >> 4) * 8;
    const int b_c = ((lane >> 3) & 1) * 8;

    float acc[4][4][4];
    #pragma unroll
    for (int i = 0; i < 4; i++)
        #pragma unroll
        for (int j = 0; j < 4; j++)
            #pragma unroll
            for (int e = 0; e < 4; e++) acc[i][j][e] = 0.f;

    const int iters = K >> 5;

    auto issue = [&](int it) {
        const int k0 = it << 5;
        const uint32_t st = sbase + (it & (GNS - 1)) * GSTAGE;
        #pragma unroll
        for (int i = 0; i < 2; i++) {
            int ch = tid + 256 * i;
            int r = ch >> 2, c = ch & 3;
            cp16(st + r * (GS * 2) + c * 16, &A[(long)(m0 + r) * lda + k0 + c * 8]);
        }
        #pragma unroll
        for (int i = 0; i < 2; i++) {
            int ch = tid + 256 * i;
            int r = ch >> 2, c = ch & 3;
            cp16(st + GTILE_B + r * (GS * 2) + c * 16, &B[(long)(n0 + r) * ldb + k0 + c * 8]);
        }
    };

    auto compute = [&](int stage) {
        const uint32_t base = sbase + (uint32_t)stage * GSTAGE;
        const uint32_t aA = base + (((wm * 64 + a_r) * GS) + a_c) * 2;
        const uint32_t aB = base + GTILE_B + (((wn * 32 + b_r) * GS) + b_c) * 2;
        #pragma unroll
        for (int ks = 0; ks < 2; ks++) {
            const uint32_t kofs = ks * 32;
            uint32_t b[4][2];
            #pragma unroll
            for (int p = 0; p < 2; p++) {
                ldsm4(b[2 * p][0], b[2 * p][1], b[2 * p + 1][0], b[2 * p + 1][1],
                      aB + p * (16 * GS * 2) + kofs);
            }
            #pragma unroll
            for (int mt = 0; mt < 4; mt++) {
                uint32_t a[4];
                ldsm4(a[0], a[1], a[2], a[3], aA + mt * (16 * GS * 2) + kofs);
                #pragma unroll
                for (int nt = 0; nt < 4; nt++)
                    mma_f16(acc[mt][nt], a, b[nt]);
            }
        }
    };

    #pragma unroll
    for (int s = 0; s < GNS - 1; s++) { issue(s); cp_commit(); }

    for (int it = 0; it < iters; ++it) {
        asm volatile("cp.async.wait_group %0;" :: "n"(GNS - 2) : "memory");
        __syncthreads();
        if (it + GNS - 1 < iters) issue(it + GNS - 1);
        cp_commit();
        compute(it & (GNS - 1));
    }

    const int g = lane >> 2;
    const int t = lane & 3;
    #pragma unroll
    for (int mt = 0; mt < 4; mt++) {
        const int r0 = m0 + wm * 64 + mt * 16 + g;
        #pragma unroll
        for (int nt = 0; nt < 4; nt++) {
            const int col = n0 + wn * 32 + nt * 8 + 2 * t;
            *(float2*)&C[(long)r0 * ldc + col] = make_float2(acc[mt][nt][0], acc[mt][nt][1]);
            *(float2*)&C[(long)(r0 + 8) * ldc + col] = make_float2(acc[mt][nt][2], acc[mt][nt][3]);
        }
    }
}

// ---------------- softmax rows of 2048: fp32 logits -> fp16 attn ----------------
__global__ __launch_bounds__(256)
void softmax2048_kernel(const float* __restrict__ logits, __half* __restrict__ attn_h)
{
    const long row = blockIdx.x;
    const float* p = logits + row * (long)N2;
    const int tid = threadIdx.x;

    float4 v0 = *(const float4*)(p + tid * 8);
    float4 v1 = *(const float4*)(p + tid * 8 + 4);

    float mx = fmaxf(fmaxf(fmaxf(v0.x, v0.y), fmaxf(v0.z, v0.w)),
                     fmaxf(fmaxf(v1.x, v1.y), fmaxf(v1.z, v1.w)));
    __shared__ float red[8];
    #pragma unroll
    for (int o = 16; o > 0; o >>= 1) mx = fmaxf(mx, __shfl_xor_sync(0xffffffffu, mx, o));
    if ((tid & 31) == 0) red[tid >> 5] = mx;
    __syncthreads();
    mx = red[0];
    #pragma unroll
    for (int i = 1; i < 8; i++) mx = fmaxf(mx, red[i]);
    __syncthreads();

    float e0 = fexp(v0.x - mx), e1 = fexp(v0.y - mx), e2 = fexp(v0.z - mx), e3 = fexp(v0.w - mx);
    float e4 = fexp(v1.x - mx), e5 = fexp(v1.y - mx), e6 = fexp(v1.z - mx), e7 = fexp(v1.w - mx);
    float s = ((e0 + e1) + (e2 + e3)) + ((e4 + e5) + (e6 + e7));
    #pragma unroll
    for (int o = 16; o > 0; o >>= 1) s += __shfl_xor_sync(0xffffffffu, s, o);
    if ((tid & 31) == 0) red[tid >> 5] = s;
    __syncthreads();
    s = 0.f;
    #pragma unroll
    for (int i = 0; i < 8; i++) s += red[i];
    const float inv = 1.0f / s;

    __half2 h[4];
    h[0] = __floats2half2_rn(e0 * inv, e1 * inv);
    h[1] = __floats2half2_rn(e2 * inv, e3 * inv);
    h[2] = __floats2half2_rn(e4 * inv, e5 * inv);
    h[3] = __floats2half2_rn(e6 * inv, e7 * inv);
    *(uint4*)(attn_h + row * (long)N2 + tid * 8) = *(uint4*)h;
}

// ---------------- fp16 transpose ----------------
__global__ __launch_bounds__(256)
void transpose_h(const __half* __restrict__ in, __half* __restrict__ out, int R, int Cc)
{
    __shared__ __half S[64][65];
    const long zin = (long)blockIdx.z * R * Cc;
    const int x0 = blockIdx.x * 64;
    const int y0 = blockIdx.y * 64;
    const int tid = threadIdx.x;

    #pragma unroll
    for (int i = 0; i < 8; i++) {
        int idx = tid + 256 * i;
        int r = idx >> 5, c2 = idx & 31;
        __half2 v = *(const __half2*)&in[zin + (long)(y0 + r) * Cc + x0 + 2 * c2];
        S[r][2 * c2] = __low2half(v);
        S[r][2 * c2 + 1] = __high2half(v);
    }
    __syncthreads();
    #pragma unroll
    for (int i = 0; i < 8; i++) {
        int idx = tid + 256 * i;
        int cc = idx >> 5, r2 = idx & 31;
        __half2 v = __halves2half2(S[2 * r2][cc], S[2 * r2 + 1][cc]);
        *(__half2*)&out[zin + (long)(x0 + cc) * R + y0 + 2 * r2] = v;
    }
}

// ---------------- fp32 -> fp16 transpose ----------------
__global__ __launch_bounds__(256)
void transpose_f2h(const float* __restrict__ in, __half* __restrict__ out, int R, int Cc)
{
    __shared__ __half S[64][65];
    const long zo = (long)blockIdx.z * R * Cc;
    const int x0 = blockIdx.x * 64;
    const int y0 = blockIdx.y * 64;
    const int tid = threadIdx.x;

    #pragma unroll
    for (int i = 0; i < 8; i++) {
        int idx = tid + 256 * i;
        int r = idx >> 5, c2 = idx & 31;
        float2 v = *(const float2*)&in[zo + (long)(y0 + r) * Cc + x0 + 2 * c2];
        S[r][2 * c2] = __float2half_rn(v.x);
        S[r][2 * c2 + 1] = __float2half_rn(v.y);
    }
    __syncthreads();
    #pragma unroll
    for (int i = 0; i < 8; i++) {
        int idx = tid + 256 * i;
        int cc = idx >> 5, r2 = idx & 31;
        __half2 v = __halves2half2(S[2 * r2][cc], S[2 * r2 + 1][cc]);
        *(__half2*)&out[zo + (long)(x0 + cc) * R + y0 + 2 * r2] = v;
    }
}

// ---------------- fp32 -> (hi, lo) fp16 convert ----------------
__global__ __launch_bounds__(256)
void convert_hl(const float* __restrict__ in, __half* __restrict__ outh,
                __half* __restrict__ outl, long n)
{
    long i = ((long)blockIdx.x * 256 + threadIdx.x) * 8;
    if (i >= n) return;
    float4 v0 = *(const float4*)&in[i];
    float4 v1 = *(const float4*)&in[i + 4];
    uint32_t h[4], l[4];
    split_h2(make_float2(v0.x, v0.y), h[0], l[0]);
    split_h2(make_float2(v0.z, v0.w), h[1], l[1]);
    split_h2(make_float2(v1.x, v1.y), h[2], l[2]);
    split_h2(make_float2(v1.z, v1.w), h[3], l[3]);
    *(uint4*)&outh[i] = make_uint4(h[0], h[1], h[2], h[3]);
    *(uint4*)&outl[i] = make_uint4(l[0], l[1], l[2], l[3]);
}

// ---------------- launcher ----------------
extern "C" void kernel_launch(void* const* d_in, const int* in_sizes, int n_in,
                              void* d_out, int out_size)
{
    const float* input1 = (const float*)d_in[0];
    const float* input2 = (const float*)d_in[1];
    const float* W_w    = (const float*)d_in[2];
    const float* W_b    = (const float*)d_in[3];

    float* out1 = (float*)d_out;
    float* out2 = out1 + (long)BATCH * N1 * DIM;

    float* attn;
    __half *attn_h, *attn_hT, *in1T, *in2T, *qh, *ql, *in2h, *in2l;
    cudaGetSymbolAddress((void**)&attn, g_attn);
    cudaGetSymbolAddress((void**)&attn_h, g_attn_h);
    cudaGetSymbolAddress((void**)&attn_hT, g_attn_hT);
    cudaGetSymbolAddress((void**)&in1T, g_in1T);
    cudaGetSymbolAddress((void**)&in2T, g_in2T);
    cudaGetSymbolAddress((void**)&qh, g_qh);
    cudaGetSymbolAddress((void**)&ql, g_ql);
    cudaGetSymbolAddress((void**)&in2h, g_in2h);
    cudaGetSymbolAddress((void**)&in2l, g_in2l);

    const int SM_H = HNS * HSTAGE;   // 81920
    const int SM_P = PNS * PSTAGE;   // 81920
    const int SM_G = GNS * GSTAGE;   // 81920

    cudaFuncSetAttribute(hgemm_split_q, cudaFuncAttributeMaxDynamicSharedMemorySize, SM_H);
    cudaFuncSetAttribute(hgemm3, cudaFuncAttributeMaxDynamicSharedMemorySize, SM_P);
    cudaFuncSetAttribute(tgemm_h2, cudaFuncAttributeMaxDynamicSharedMemorySize, SM_G);

    // Prep: transposes (K4/K5), hi/lo convert of input2 (K2)
    transpose_f2h<<<dim3(DIM / 64, N1 / 64, BATCH), 256>>>(input1, in1T, N1, DIM);
    transpose_f2h<<<dim3(DIM / 64, N2 / 64, BATCH), 256>>>(input2, in2T, N2, DIM);
    {
        long n2 = (long)BATCH * N2 * DIM;
        convert_hl<<<(int)(n2 / (256 * 8)), 256>>>(input2, in2h, in2l, n2);
    }

    // K1: q = input1 @ W^T + b  -> qh/ql directly (split epilogue)
    hgemm_split_q<<<dim3(DIM / 128, (BATCH * N1) / 128, 1), 256, SM_H>>>(
        input1, W_w, W_b, qh, ql, DIM, DIM, DIM, DIM);

    // K2: logits = q @ input2^T per batch (3-term pre-split, ldmatrix)
    hgemm3<<<dim3(N2 / 128, N1 / 128, BATCH), 256, SM_P>>>(
        qh, ql, in2h, in2l, attn, DIM, DIM, DIM, N2,
        (long)N1 * DIM, (long)N2 * DIM, (long)N1 * N2);

    // softmax: fp32 logits -> fp16 attn
    softmax2048_kernel<<<BATCH * N1, 256>>>(attn, attn_h);

    // attn^T (materialized)
    transpose_h<<<dim3(N2 / 64, N1 / 64, BATCH), 256>>>(attn_h, attn_hT, N1, N2);

    // K4 + K5 fused
    tgemm_h2<<<dim3(DIM / 128, N1 / 128, 2 * BATCH), 256, SM_G>>>(
        attn_h, in2T, out1,
        attn_hT, in1T, out2,
        N2, N2, N2, DIM,
        (long)N1 * N2, (long)DIM * N2, (long)N1 * DIM);
}